// round 1
// baseline (speedup 1.0000x reference)
#include <cuda_runtime.h>

#define B_   16
#define C_   512
#define N_   1681
#define CK_  256
#define NT_  27          // ceil(1681/64)
#define SCALE_ 0.0625f   // 1/sqrt(256)
#define EPS_  1e-5f

// ---- scratch (device globals; no allocation allowed) ----
__device__ float g_Q[B_ * N_ * CK_];                 // [b, n, k]
__device__ float g_K[B_ * N_ * CK_];                 // [b, m, k]
__device__ float g_S[(size_t)B_ * N_ * N_];          // sim1 = qk*scale*fg, [b, n, m]
__device__ float g_pss[B_ * NT_ * N_];               // partial sum sim1*fg per m-tile
__device__ float g_pfs[B_ * NT_ * N_];               // partial sum fg per m-tile
__device__ float g_pmin[B_ * NT_ * N_];              // partial min sim1 per m-tile
__device__ float g_inv[B_ * N_];                     // 1/(D+eps)
__device__ float g_minv[B_ * N_];                    // row min

// ============================================================
// Kernel 1: projections  O[b,n,k] = sum_c x[b,c,n]*W[k,c] + bias[k]
// grid: (27 n-tiles, 4 k-tiles, 32 = b*2 + {Q,K}); block 256
// ============================================================
__global__ __launch_bounds__(256)
void proj_kernel(const float* __restrict__ x,
                 const float* __restrict__ Wq, const float* __restrict__ bq,
                 const float* __restrict__ Wk, const float* __restrict__ bk)
{
    int bz  = blockIdx.z;
    int b   = bz >> 1;
    int isK = bz & 1;
    const float* W    = isK ? Wk : Wq;
    const float* bias = isK ? bk : bq;
    float*       O    = isK ? g_K : g_Q;

    int n0 = blockIdx.x * 64;
    int k0 = blockIdx.y * 64;

    __shared__ __align__(16) float As[16][68];  // As[cc][nn] = x[b, c0+cc, n0+nn]
    __shared__ __align__(16) float Bs[16][68];  // Bs[cc][kk] = W[k0+kk, c0+cc]

    int t  = threadIdx.x;
    int tx = t & 15, ty = t >> 4;
    float acc[4][4] = {};
    const float* xb = x + (size_t)b * C_ * N_;

    for (int c0 = 0; c0 < C_; c0 += 16) {
        {   // load x tile, coalesced over n
            int nn  = t & 63;
            int cc0 = t >> 6;
            int n   = n0 + nn;
            #pragma unroll
            for (int r = 0; r < 4; r++) {
                int cc = cc0 + r * 4;
                As[cc][nn] = (n < N_) ? xb[(size_t)(c0 + cc) * N_ + n] : 0.f;
            }
        }
        {   // load W tile, coalesced over c
            int cc  = t & 15;
            int kk0 = t >> 4;
            #pragma unroll
            for (int r = 0; r < 4; r++) {
                int kk = kk0 + r * 16;
                Bs[cc][kk] = W[(size_t)(k0 + kk) * C_ + c0 + cc];
            }
        }
        __syncthreads();
        #pragma unroll
        for (int cc = 0; cc < 16; cc++) {
            float4 a4 = *(const float4*)&As[cc][ty * 4];
            float4 b4 = *(const float4*)&Bs[cc][tx * 4];
            float a[4] = {a4.x, a4.y, a4.z, a4.w};
            float bb[4] = {b4.x, b4.y, b4.z, b4.w};
            #pragma unroll
            for (int i = 0; i < 4; i++)
                #pragma unroll
                for (int j = 0; j < 4; j++)
                    acc[i][j] += a[i] * bb[j];
        }
        __syncthreads();
    }
    #pragma unroll
    for (int i = 0; i < 4; i++) {
        int n = n0 + ty * 4 + i;
        if (n < N_) {
            #pragma unroll
            for (int j = 0; j < 4; j++) {
                int k = k0 + tx * 4 + j;
                O[((size_t)b * N_ + n) * CK_ + k] = acc[i][j] + bias[k];
            }
        }
    }
}

// ============================================================
// Kernel 2: sim1[b,n,m] = (Q[b,n,:] . K[b,m,:]) * scale * fg[b,n,m]
// + per-(m-tile) row partials: min(sim1), sum(sim1*fg), sum(fg)
// grid: (27 m-tiles, 27 n-tiles, 16 b); block 256
// ============================================================
__global__ __launch_bounds__(256)
void sim_kernel(const float* __restrict__ fg)
{
    int b  = blockIdx.z;
    int n0 = blockIdx.y * 64;
    int m0 = blockIdx.x * 64;

    __shared__ __align__(16) float As[16][68];  // As[kk][nn]
    __shared__ __align__(16) float Bs[16][68];  // Bs[kk][mm]

    int t  = threadIdx.x;
    int tx = t & 15, ty = t >> 4;
    float acc[4][4] = {};
    const float* Qb = g_Q + (size_t)b * N_ * CK_;
    const float* Kb = g_K + (size_t)b * N_ * CK_;

    for (int k0 = 0; k0 < CK_; k0 += 16) {
        {
            int col  = t & 15;
            int row0 = t >> 4;
            #pragma unroll
            for (int r = 0; r < 4; r++) {
                int row = row0 + r * 16;
                int n = n0 + row;
                As[col][row] = (n < N_) ? Qb[(size_t)n * CK_ + k0 + col] : 0.f;
                int m = m0 + row;
                Bs[col][row] = (m < N_) ? Kb[(size_t)m * CK_ + k0 + col] : 0.f;
            }
        }
        __syncthreads();
        #pragma unroll
        for (int kk = 0; kk < 16; kk++) {
            float4 a4 = *(const float4*)&As[kk][ty * 4];
            float4 b4 = *(const float4*)&Bs[kk][tx * 4];
            float a[4] = {a4.x, a4.y, a4.z, a4.w};
            float bb[4] = {b4.x, b4.y, b4.z, b4.w};
            #pragma unroll
            for (int i = 0; i < 4; i++)
                #pragma unroll
                for (int j = 0; j < 4; j++)
                    acc[i][j] += a[i] * bb[j];
        }
        __syncthreads();
    }

    // epilogue: apply scale*fg, store sim1, compute row partials
    const float* fgb = fg + (size_t)b * N_ * N_;
    float*       Sb  = g_S + (size_t)b * N_ * N_;
    float rmin[4], rss[4], rfs[4];
    #pragma unroll
    for (int i = 0; i < 4; i++) { rmin[i] = 3.4e38f; rss[i] = 0.f; rfs[i] = 0.f; }

    #pragma unroll
    for (int i = 0; i < 4; i++) {
        int n = n0 + ty * 4 + i;
        if (n < N_) {
            #pragma unroll
            for (int j = 0; j < 4; j++) {
                int m = m0 + tx * 4 + j;
                if (m < N_) {
                    size_t off = (size_t)n * N_ + m;
                    float f  = fgb[off];
                    float s1 = acc[i][j] * SCALE_ * f;
                    Sb[off]  = s1;
                    rmin[i]  = fminf(rmin[i], s1);
                    rss[i]  += s1 * f;
                    rfs[i]  += f;
                }
            }
        }
    }
    // reduce across 16 threads sharing the same rows (contiguous 16-lane group)
    #pragma unroll
    for (int i = 0; i < 4; i++) {
        #pragma unroll
        for (int off = 8; off > 0; off >>= 1) {
            rmin[i] = fminf(rmin[i], __shfl_down_sync(0xFFFFFFFFu, rmin[i], off, 16));
            rss[i] += __shfl_down_sync(0xFFFFFFFFu, rss[i], off, 16);
            rfs[i] += __shfl_down_sync(0xFFFFFFFFu, rfs[i], off, 16);
        }
        if (tx == 0) {
            int n = n0 + ty * 4 + i;
            if (n < N_) {
                size_t idx = ((size_t)b * NT_ + blockIdx.x) * N_ + n;
                g_pmin[idx] = rmin[i];
                g_pss[idx]  = rss[i];
                g_pfs[idx]  = rfs[i];
            }
        }
    }
}

// ============================================================
// Kernel 3: finalize per-row stats
// ============================================================
__global__ __launch_bounds__(256)
void fin_stats()
{
    int i = blockIdx.x * blockDim.x + threadIdx.x;
    if (i >= B_ * N_) return;
    int b = i / N_;
    int n = i - b * N_;
    float mn = 3.4e38f, ss = 0.f, fs = 0.f;
    #pragma unroll 1
    for (int tile = 0; tile < NT_; tile++) {
        size_t idx = ((size_t)b * NT_ + tile) * N_ + n;
        mn = fminf(mn, g_pmin[idx]);
        ss += g_pss[idx];
        fs += g_pfs[idx];
    }
    float D = ss - mn * fs;
    g_inv[i]  = 1.f / (D + EPS_);
    g_minv[i] = mn;
}

// ============================================================
// Kernel 4: context GEMM with on-the-fly A-transform + fuse epilogue
// A[n,m] = (sim1 - min_n)*fg*inv_n + bg ; ctx = A @ V, V[m,c] = x[b,c,m]
// out[b,c,n] = gamma*ctx[n,c] + x[b,c,n]
// grid: (27 n-tiles, 8 c-tiles, 16 b); block 256
// ============================================================
__global__ __launch_bounds__(256)
void ctx_kernel(const float* __restrict__ x,
                const float* __restrict__ fg,
                const float* __restrict__ bg,
                const float* __restrict__ gamma,
                float* __restrict__ out)
{
    int b  = blockIdx.z;
    int n0 = blockIdx.x * 64;
    int c0 = blockIdx.y * 64;

    __shared__ __align__(16) float As[16][68];  // As[mm][nn] (transformed A)
    __shared__ __align__(16) float Bs[16][68];  // Bs[mm][cc] (V)
    __shared__ float s_inv[64], s_minv[64];

    int t  = threadIdx.x;
    int tx = t & 15, ty = t >> 4;

    if (t < 64) {
        int n = n0 + t;
        s_inv[t]  = (n < N_) ? g_inv[b * N_ + n]  : 0.f;
        s_minv[t] = (n < N_) ? g_minv[b * N_ + n] : 0.f;
    }
    __syncthreads();

    float acc[4][4] = {};
    const float* xb  = x  + (size_t)b * C_ * N_;
    const float* Sb  = g_S + (size_t)b * N_ * N_;
    const float* fgb = fg + (size_t)b * N_ * N_;
    const float* bgb = bg + (size_t)b * N_ * N_;

    for (int m0 = 0; m0 < N_; m0 += 16) {
        int mm = t & 15;
        int m  = m0 + mm;
        {   // A tile (coalesced over m)
            int nn0 = t >> 4;
            #pragma unroll
            for (int r = 0; r < 4; r++) {
                int nn = nn0 + r * 16;
                int n  = n0 + nn;
                float a = 0.f;
                if (n < N_ && m < N_) {
                    size_t off = (size_t)n * N_ + m;
                    float s1 = Sb[off];
                    float f  = fgb[off];
                    float g  = bgb[off];
                    a = (s1 - s_minv[nn]) * f * s_inv[nn] + g;
                }
                As[mm][nn] = a;
            }
        }
        {   // V tile (coalesced over m)
            int cc0 = t >> 4;
            #pragma unroll
            for (int r = 0; r < 4; r++) {
                int cc = cc0 + r * 16;
                Bs[mm][cc] = (m < N_) ? xb[(size_t)(c0 + cc) * N_ + m] : 0.f;
            }
        }
        __syncthreads();
        #pragma unroll
        for (int k = 0; k < 16; k++) {
            float4 a4 = *(const float4*)&As[k][ty * 4];
            float4 b4 = *(const float4*)&Bs[k][tx * 4];
            float a[4] = {a4.x, a4.y, a4.z, a4.w};
            float bb[4] = {b4.x, b4.y, b4.z, b4.w};
            #pragma unroll
            for (int i = 0; i < 4; i++)
                #pragma unroll
                for (int j = 0; j < 4; j++)
                    acc[i][j] += a[i] * bb[j];
        }
        __syncthreads();
    }

    float gam = gamma[0];
    #pragma unroll
    for (int i = 0; i < 4; i++) {
        int n = n0 + ty * 4 + i;
        if (n < N_) {
            #pragma unroll
            for (int j = 0; j < 4; j++) {
                int c = c0 + tx * 4 + j;
                size_t o = (size_t)b * C_ * N_ + (size_t)c * N_ + n;
                out[o] = gam * acc[i][j] + x[o];
            }
        }
    }
}

// ============================================================
extern "C" void kernel_launch(void* const* d_in, const int* in_sizes, int n_in,
                              void* d_out, int out_size)
{
    const float* x     = (const float*)d_in[0];
    const float* fg    = (const float*)d_in[1];
    const float* bg    = (const float*)d_in[2];
    const float* Wq    = (const float*)d_in[3];
    const float* bq    = (const float*)d_in[4];
    const float* Wk    = (const float*)d_in[5];
    const float* bk    = (const float*)d_in[6];
    const float* gamma = (const float*)d_in[7];
    float* out = (float*)d_out;

    dim3 gp(NT_, CK_ / 64, B_ * 2);
    proj_kernel<<<gp, 256>>>(x, Wq, bq, Wk, bk);

    dim3 gs(NT_, NT_, B_);
    sim_kernel<<<gs, 256>>>(fg);

    fin_stats<<<(B_ * N_ + 255) / 256, 256>>>();

    dim3 gc(NT_, C_ / 64, B_);
    ctx_kernel<<<gc, 256>>>(x, fg, bg, gamma, out);
}